// round 3
// baseline (speedup 1.0000x reference)
#include <cuda_runtime.h>
#include <cuda_bf16.h>
#include <cstdint>

#define N_NODES 50000
#define HIDDEN 128
#define N_REL 9
#define N_LAYERS 3
#define N_EDGES 600000
#define TILE_M 128
#define MAX_TILES 4800

// ---------------- device scratch (no allocations allowed) ----------------
__device__ float g_buf[2][N_NODES * HIDDEN];   // layer ping-pong buffers
__device__ int g_srcS[N_EDGES];                // src sorted by relation
__device__ int g_dstS[N_EDGES];                // dst sorted by relation
__device__ int g_cnt[N_NODES * N_REL];         // per (node, rel) in-degree
__device__ int g_relCount[N_REL];
__device__ int g_relCursor[N_REL];
__device__ int g_tileRel[MAX_TILES];
__device__ int g_tileStart[MAX_TILES];
__device__ int g_tileCnt[MAX_TILES];
__device__ int g_numTiles;

// ---------------- helpers ----------------
__device__ __forceinline__ uint32_t smem_u32(const void* p) {
    uint32_t a;
    asm("{ .reg .u64 t; cvta.to.shared.u64 t, %1; cvt.u32.u64 %0, t; }" : "=r"(a) : "l"(p));
    return a;
}

// 256-byte rows, XOR-swizzle the 16B group index with (row & 7) -> conflict-free
// ldmatrix column accesses across any 8 consecutive rows.
__device__ __forceinline__ uint32_t swz(int row, int colByte) {
    return (uint32_t)(row * 256 + (colByte ^ ((row & 7) << 4)));
}

__device__ __forceinline__ uint4 cvt8(float4 x, float4 y, int relu) {
    if (relu) {
        x.x = fmaxf(x.x, 0.f); x.y = fmaxf(x.y, 0.f);
        x.z = fmaxf(x.z, 0.f); x.w = fmaxf(x.w, 0.f);
        y.x = fmaxf(y.x, 0.f); y.y = fmaxf(y.y, 0.f);
        y.z = fmaxf(y.z, 0.f); y.w = fmaxf(y.w, 0.f);
    }
    __nv_bfloat162 b0 = __floats2bfloat162_rn(x.x, x.y);
    __nv_bfloat162 b1 = __floats2bfloat162_rn(x.z, x.w);
    __nv_bfloat162 b2 = __floats2bfloat162_rn(y.x, y.y);
    __nv_bfloat162 b3 = __floats2bfloat162_rn(y.z, y.w);
    uint4 u;
    u.x = *(unsigned*)&b0; u.y = *(unsigned*)&b1;
    u.z = *(unsigned*)&b2; u.w = *(unsigned*)&b3;
    return u;
}

// ---------------- pre-pass kernels ----------------
__global__ void k_hist(const int* __restrict__ ei, const int* __restrict__ et) {
    __shared__ int sh[N_REL];
    int tid = threadIdx.x;
    if (tid < N_REL) sh[tid] = 0;
    __syncthreads();
    int e = blockIdx.x * blockDim.x + tid;
    if (e < N_EDGES) {
        int t = et[e];
        int d = ei[e];
        atomicAdd(&g_cnt[d * N_REL + t], 1);
        atomicAdd(&sh[t], 1);
    }
    __syncthreads();
    if (tid < N_REL && sh[tid]) atomicAdd(&g_relCount[tid], sh[tid]);
}

__global__ void k_tiles() {
    __shared__ int offs[N_REL + 1], toffs[N_REL + 1];
    if (threadIdx.x == 0) {
        int o = 0, to = 0;
        for (int r = 0; r < N_REL; r++) {
            offs[r] = o; toffs[r] = to;
            g_relCursor[r] = o;
            int c = g_relCount[r];
            o += c;
            to += (c + TILE_M - 1) / TILE_M;
        }
        offs[N_REL] = o; toffs[N_REL] = to;
        g_numTiles = to;
    }
    __syncthreads();
    for (int r = 0; r < N_REL; r++) {
        int c = g_relCount[r];
        int nt = (c + TILE_M - 1) / TILE_M;
        for (int i = threadIdx.x; i < nt; i += blockDim.x) {
            int t = toffs[r] + i;
            g_tileRel[t] = r;
            g_tileStart[t] = offs[r] + i * TILE_M;
            g_tileCnt[t] = min(TILE_M, c - i * TILE_M);
        }
    }
}

__global__ void k_scatter(const int* __restrict__ ei, const int* __restrict__ et) {
    __shared__ int sCnt[N_REL], sBase[N_REL];
    int tid = threadIdx.x;
    if (tid < N_REL) sCnt[tid] = 0;
    __syncthreads();
    int e = blockIdx.x * blockDim.x + tid;
    int t = 0, loc = 0, s = 0, d = 0;
    bool v = (e < N_EDGES);
    if (v) {
        t = et[e]; d = ei[e]; s = ei[N_EDGES + e];
        loc = atomicAdd(&sCnt[t], 1);
    }
    __syncthreads();
    if (tid < N_REL && sCnt[tid] > 0) sBase[tid] = atomicAdd(&g_relCursor[tid], sCnt[tid]);
    __syncthreads();
    if (v) {
        int pos = sBase[t] + loc;
        g_srcS[pos] = s;
        g_dstS[pos] = d;
    }
}

// hidden[d][f] = sum_r cnt[d][r] * bias[r][f]  (also zero-inits untouched rows)
__global__ void k_bias(const float* __restrict__ bias, float* __restrict__ out) {
    int d = blockIdx.x, f = threadIdx.x;
    const int* c = &g_cnt[d * N_REL];
    float acc = 0.f;
#pragma unroll
    for (int r = 0; r < N_REL; r++) acc += (float)__ldg(&c[r]) * __ldg(&bias[r * HIDDEN + f]);
    out[d * HIDDEN + f] = acc;
}

// ---------------- fused gather + mma.sync + scatter ----------------
static constexpr int SM_W = 0;       // 32 KB: W_r bf16 swizzled ([k][n] rows)
static constexpr int SM_A = 32768;   // 32 KB: gathered A tile ([m][k] rows)
static constexpr int SMEM_DYN = 65536 + 1024;  // + align slack

__global__ void __launch_bounds__(256, 2)
k_fused(const float* __restrict__ in, float* __restrict__ out,
        const float* __restrict__ W, int relu) {
    extern __shared__ char smraw[];
    uint32_t sbRaw = smem_u32(smraw);
    uint32_t sb = (sbRaw + 255) & ~255u;
    char* sm = smraw + (sb - sbRaw);
    int tid = threadIdx.x, wid = tid >> 5, lid = tid & 31;

    int T = g_numTiles;
    int per = (T + gridDim.x - 1) / gridDim.x;
    int t0 = blockIdx.x * per;
    int t1 = min(T, t0 + per);

    int curRel = -1;
    int row = tid >> 1, h = tid & 1;     // gather assignment: 2 threads per row
    int m0 = wid * 16;                   // this warp's output row slab

    for (int t = t0; t < t1; t++) {
        int r = g_tileRel[t];
        __syncthreads();   // previous tile's ldmatrix reads done before overwriting smem
        if (r != curRel) {
            // load W_r as [k][n] bf16 rows, swizzled
            const float* Wr = W + (size_t)r * HIDDEN * HIDDEN;
            {
                const float4* w4 = (const float4*)(Wr + row * HIDDEN + h * 64);
#pragma unroll
                for (int i = 0; i < 8; i++) {
                    float4 x = w4[2 * i], y = w4[2 * i + 1];
                    *(uint4*)(sm + SM_W + swz(row, h * 128 + i * 16)) = cvt8(x, y, 0);
                }
            }
            curRel = r;
        }
        int start = g_tileStart[t], cnt = g_tileCnt[t];
        // gather A tile: row = edge slot, 128 bf16 features per row
        if (row < cnt) {
            const float4* s4 = (const float4*)(in + (size_t)g_srcS[start + row] * HIDDEN + h * 64);
#pragma unroll
            for (int i = 0; i < 8; i++) {
                float4 x = s4[2 * i], y = s4[2 * i + 1];
                *(uint4*)(sm + SM_A + swz(row, h * 128 + i * 16)) = cvt8(x, y, relu);
            }
        } else {
            uint4 z = make_uint4(0, 0, 0, 0);
#pragma unroll
            for (int i = 0; i < 8; i++)
                *(uint4*)(sm + SM_A + swz(row, h * 128 + i * 16)) = z;
        }
        __syncthreads();

        // ---- 16x128x128 per warp via m16n8k16 ----
        float c[16][4];
#pragma unroll
        for (int nn = 0; nn < 16; nn++)
#pragma unroll
            for (int j = 0; j < 4; j++) c[nn][j] = 0.f;

#pragma unroll
        for (int kk = 0; kk < 8; kk++) {
            uint32_t a0, a1, a2, a3;
            uint32_t aaddr = sb + SM_A + swz(m0 + (lid & 15), kk * 32 + (lid >> 4) * 16);
            asm volatile("ldmatrix.sync.aligned.m8n8.x4.shared.b16 {%0,%1,%2,%3}, [%4];"
                         : "=r"(a0), "=r"(a1), "=r"(a2), "=r"(a3) : "r"(aaddr));
#pragma unroll
            for (int nn = 0; nn < 8; nn++) {
                uint32_t b0, b1, b2, b3;
                uint32_t baddr = sb + SM_W + swz(kk * 16 + (lid & 15), nn * 32 + (lid >> 4) * 16);
                asm volatile("ldmatrix.sync.aligned.m8n8.x4.trans.shared.b16 {%0,%1,%2,%3}, [%4];"
                             : "=r"(b0), "=r"(b1), "=r"(b2), "=r"(b3) : "r"(baddr));
                asm volatile("mma.sync.aligned.m16n8k16.row.col.f32.bf16.bf16.f32 "
                             "{%0,%1,%2,%3}, {%4,%5,%6,%7}, {%8,%9}, {%0,%1,%2,%3};"
                             : "+f"(c[2 * nn][0]), "+f"(c[2 * nn][1]),
                               "+f"(c[2 * nn][2]), "+f"(c[2 * nn][3])
                             : "r"(a0), "r"(a1), "r"(a2), "r"(a3), "r"(b0), "r"(b1));
                asm volatile("mma.sync.aligned.m16n8k16.row.col.f32.bf16.bf16.f32 "
                             "{%0,%1,%2,%3}, {%4,%5,%6,%7}, {%8,%9}, {%0,%1,%2,%3};"
                             : "+f"(c[2 * nn + 1][0]), "+f"(c[2 * nn + 1][1]),
                               "+f"(c[2 * nn + 1][2]), "+f"(c[2 * nn + 1][3])
                             : "r"(a0), "r"(a1), "r"(a2), "r"(a3), "r"(b2), "r"(b3));
            }
        }

        // ---- scatter: red.global.add directly from accumulators ----
        int r0 = m0 + (lid >> 2);
        int r1 = r0 + 8;
        int col0 = (lid & 3) * 2;
        bool act0 = r0 < cnt, act1 = r1 < cnt;
        float* p0 = act0 ? out + (size_t)g_dstS[start + r0] * HIDDEN + col0 : nullptr;
        float* p1 = act1 ? out + (size_t)g_dstS[start + r1] * HIDDEN + col0 : nullptr;
#pragma unroll
        for (int nn = 0; nn < 16; nn++) {
            if (act0)
                asm volatile("red.global.add.v2.f32 [%0], {%1,%2};"
                             :: "l"(p0 + nn * 8), "f"(c[nn][0]), "f"(c[nn][1]) : "memory");
            if (act1)
                asm volatile("red.global.add.v2.f32 [%0], {%1,%2};"
                             :: "l"(p1 + nn * 8), "f"(c[nn][2]), "f"(c[nn][3]) : "memory");
        }
    }
}

// ---------------- launch ----------------
extern "C" void kernel_launch(void* const* d_in, const int* in_sizes, int n_in,
                              void* d_out, int out_size) {
    const int* ei = (const int*)d_in[0];     // [2, E]: row0 = dest, row1 = src
    const int* et = (const int*)d_in[1];     // [E]
    const float* emb = (const float*)d_in[2];// [N, H]
    const float* Wt = (const float*)d_in[3]; // [L, R, H, H]
    const float* Bi = (const float*)d_in[4]; // [L, R, H]
    float* out = (float*)d_out;              // [N, H]
    (void)in_sizes; (void)n_in; (void)out_size;

    void* pc; cudaGetSymbolAddress(&pc, g_cnt);
    void* prc; cudaGetSymbolAddress(&prc, g_relCount);
    void* pbuf; cudaGetSymbolAddress(&pbuf, g_buf);
    float* bufA = (float*)pbuf;
    float* bufB = bufA + (size_t)N_NODES * HIDDEN;

    cudaMemsetAsync(pc, 0, (size_t)N_NODES * N_REL * sizeof(int));
    cudaMemsetAsync(prc, 0, N_REL * sizeof(int));

    int eb = (N_EDGES + 255) / 256;
    k_hist<<<eb, 256>>>(ei, et);
    k_tiles<<<1, 256>>>();
    k_scatter<<<eb, 256>>>(ei, et);

    cudaFuncSetAttribute(k_fused, cudaFuncAttributeMaxDynamicSharedMemorySize, SMEM_DYN);

    const float* lin[N_LAYERS] = {emb, bufA, bufB};
    float* lout[N_LAYERS] = {bufA, bufB, out};
    for (int l = 0; l < N_LAYERS; l++) {
        k_bias<<<N_NODES, 128>>>(Bi + (size_t)l * N_REL * HIDDEN, lout[l]);
        k_fused<<<296, 256, SMEM_DYN>>>(lin[l], lout[l],
                                        Wt + (size_t)l * N_REL * HIDDEN * HIDDEN,
                                        l > 0 ? 1 : 0);
    }
}

// round 6
// speedup vs baseline: 1.3246x; 1.3246x over previous
#include <cuda_runtime.h>
#include <cuda_bf16.h>
#include <cstdint>

#define N_NODES 50000
#define HIDDEN 128
#define N_REL 9
#define N_LAYERS 3
#define N_EDGES 600000
#define TILE_M 128
#define MAX_TILES 4800

// ---------------- device scratch (no allocations allowed) ----------------
__device__ float g_buf[2][N_NODES * HIDDEN];          // layer ping-pong fp32
__device__ __nv_bfloat16 g_inb[N_NODES * HIDDEN];     // bf16 layer input
__device__ char g_wbf[N_LAYERS * N_REL * 32768];      // pre-swizzled bf16 weights
__device__ int g_srcS[N_EDGES];
__device__ int g_dstS[N_EDGES];
__device__ int g_cnt[N_NODES * N_REL];
__device__ int g_relCount[N_REL];
__device__ int g_relCursor[N_REL];
__device__ int g_tileRel[MAX_TILES];
__device__ int g_tileStart[MAX_TILES];
__device__ int g_tileCnt[MAX_TILES];
__device__ int g_numTiles;

// ---------------- helpers ----------------
__device__ __forceinline__ uint32_t smem_u32(const void* p) {
    uint32_t a;
    asm("{ .reg .u64 t; cvta.to.shared.u64 t, %1; cvt.u32.u64 %0, t; }" : "=r"(a) : "l"(p));
    return a;
}

// 256-byte rows, XOR-swizzle 16B group index with (row & 7): conflict-free ldmatrix
__device__ __forceinline__ uint32_t swz(int row, int colByte) {
    return (uint32_t)(row * 256 + (colByte ^ ((row & 7) << 4)));
}

__device__ __forceinline__ uint4 cvt8(float4 x, float4 y, int relu) {
    if (relu) {
        x.x = fmaxf(x.x, 0.f); x.y = fmaxf(x.y, 0.f);
        x.z = fmaxf(x.z, 0.f); x.w = fmaxf(x.w, 0.f);
        y.x = fmaxf(y.x, 0.f); y.y = fmaxf(y.y, 0.f);
        y.z = fmaxf(y.z, 0.f); y.w = fmaxf(y.w, 0.f);
    }
    __nv_bfloat162 b0 = __floats2bfloat162_rn(x.x, x.y);
    __nv_bfloat162 b1 = __floats2bfloat162_rn(x.z, x.w);
    __nv_bfloat162 b2 = __floats2bfloat162_rn(y.x, y.y);
    __nv_bfloat162 b3 = __floats2bfloat162_rn(y.z, y.w);
    uint4 u;
    u.x = *(unsigned*)&b0; u.y = *(unsigned*)&b1;
    u.z = *(unsigned*)&b2; u.w = *(unsigned*)&b3;
    return u;
}

// ---------------- pre-pass kernels ----------------
__global__ void k_hist(const int* __restrict__ ei, const int* __restrict__ et) {
    __shared__ int sh[N_REL];
    int tid = threadIdx.x;
    if (tid < N_REL) sh[tid] = 0;
    __syncthreads();
    int e = blockIdx.x * blockDim.x + tid;
    if (e < N_EDGES) {
        int t = et[e];
        int d = ei[e];
        atomicAdd(&g_cnt[d * N_REL + t], 1);
        atomicAdd(&sh[t], 1);
    }
    __syncthreads();
    if (tid < N_REL && sh[tid]) atomicAdd(&g_relCount[tid], sh[tid]);
}

__global__ void k_tiles() {
    __shared__ int offs[N_REL + 1], toffs[N_REL + 1];
    if (threadIdx.x == 0) {
        int o = 0, to = 0;
        for (int r = 0; r < N_REL; r++) {
            offs[r] = o; toffs[r] = to;
            g_relCursor[r] = o;
            int c = g_relCount[r];
            o += c;
            to += (c + TILE_M - 1) / TILE_M;
        }
        offs[N_REL] = o; toffs[N_REL] = to;
        g_numTiles = to;
    }
    __syncthreads();
    for (int r = 0; r < N_REL; r++) {
        int c = g_relCount[r];
        int nt = (c + TILE_M - 1) / TILE_M;
        for (int i = threadIdx.x; i < nt; i += blockDim.x) {
            int t = toffs[r] + i;
            g_tileRel[t] = r;
            g_tileStart[t] = offs[r] + i * TILE_M;
            g_tileCnt[t] = min(TILE_M, c - i * TILE_M);
        }
    }
}

__global__ void k_scatter(const int* __restrict__ ei, const int* __restrict__ et) {
    __shared__ int sCnt[N_REL], sBase[N_REL];
    int tid = threadIdx.x;
    if (tid < N_REL) sCnt[tid] = 0;
    __syncthreads();
    int e = blockIdx.x * blockDim.x + tid;
    int t = 0, loc = 0, s = 0, d = 0;
    bool v = (e < N_EDGES);
    if (v) {
        t = et[e]; d = ei[e]; s = ei[N_EDGES + e];
        loc = atomicAdd(&sCnt[t], 1);
    }
    __syncthreads();
    if (tid < N_REL && sCnt[tid] > 0) sBase[tid] = atomicAdd(&g_relCursor[tid], sCnt[tid]);
    __syncthreads();
    if (v) {
        int pos = sBase[t] + loc;
        g_srcS[pos] = s;
        g_dstS[pos] = d;
    }
}

// pre-swizzle W[l][r] -> bf16 blocks matching smem layout (one block per (l,r))
__global__ void k_wcvt(const float* __restrict__ W) {
    int blk = blockIdx.x;                 // l*N_REL + r
    int tid = threadIdx.x;
    int row = tid >> 1, h = tid & 1;      // row = k index
    const float* src = W + ((size_t)blk * HIDDEN + row) * HIDDEN + h * 64;
    char* dst = g_wbf + (size_t)blk * 32768;
#pragma unroll
    for (int i = 0; i < 8; i++) {
        // group i covers floats [8i, 8i+8) of this 64-float half-row
        float4 x = *(const float4*)(src + i * 8);
        float4 y = *(const float4*)(src + i * 8 + 4);
        *(uint4*)(dst + swz(row, h * 128 + i * 16)) = cvt8(x, y, 0);
    }
}

// fp32 layer input -> bf16 (relu fused)
__global__ void k_cvt(const float* __restrict__ in, int relu) {
    int i = blockIdx.x * blockDim.x + threadIdx.x;   // index of 8-float group
    if (i < N_NODES * HIDDEN / 8) {
        const float4* s = (const float4*)(in + (size_t)i * 8);
        float4 x = s[0], y = s[1];
        *(uint4*)(g_inb + (size_t)i * 8) = cvt8(x, y, relu);
    }
}

// hidden[d][f] = sum_r cnt[d][r] * bias[r][f]  -- warp per node, bias in smem
__global__ void k_bias(const float* __restrict__ bias, float* __restrict__ out) {
    __shared__ float sb[N_REL * HIDDEN];
    int tid = threadIdx.x, wid = tid >> 5, lid = tid & 31;
    for (int i = tid; i < N_REL * HIDDEN; i += blockDim.x) sb[i] = bias[i];
    __syncthreads();
    int warps = gridDim.x * (blockDim.x >> 5);
    for (int node = blockIdx.x * (blockDim.x >> 5) + wid; node < N_NODES; node += warps) {
        const int* c = &g_cnt[node * N_REL];
        float4 acc = make_float4(0.f, 0.f, 0.f, 0.f);
#pragma unroll
        for (int r = 0; r < N_REL; r++) {
            float cf = (float)__ldg(&c[r]);
            float4 b = *(const float4*)&sb[r * HIDDEN + lid * 4];
            acc.x += cf * b.x; acc.y += cf * b.y;
            acc.z += cf * b.z; acc.w += cf * b.w;
        }
        *(float4*)&out[(size_t)node * HIDDEN + lid * 4] = acc;
    }
}

// ---------------- fused gather + mma.sync + scatter (cp.async pipelined) -------
static constexpr int SM_W = 0;       // 32 KB: W_r bf16 swizzled
static constexpr int SM_A0 = 32768;  // 32 KB: A tile buf 0
static constexpr int SM_A1 = 65536;  // 32 KB: A tile buf 1
static constexpr int SMEM_DYN = 98304 + 512;

__device__ __forceinline__ void issue_gather(const char* inb, uint32_t sbA,
                                             int start, int cnt, int row, int h) {
    int sz = (row < cnt) ? 16 : 0;
    int node = (row < cnt) ? g_srcS[start + row] : 0;
    const char* src = inb + (size_t)node * 256 + h * 128;
#pragma unroll
    for (int i = 0; i < 8; i++) {
        uint32_t dst = sbA + swz(row, h * 128 + i * 16);
        asm volatile("cp.async.cg.shared.global [%0], [%1], 16, %2;"
                     :: "r"(dst), "l"(src + i * 16), "r"(sz));
    }
}

__global__ void __launch_bounds__(256, 2)
k_fused(const char* __restrict__ wswz, float* __restrict__ out) {
    extern __shared__ char smraw[];
    uint32_t sbRaw = smem_u32(smraw);
    uint32_t sb = (sbRaw + 255) & ~255u;
    int tid = threadIdx.x, wid = tid >> 5, lid = tid & 31;

    const char* inb = (const char*)g_inb;

    int T = g_numTiles;
    int per = (T + gridDim.x - 1) / gridDim.x;
    int t0 = blockIdx.x * per;
    int t1 = min(T, t0 + per);
    if (t0 >= t1) return;

    int row = tid >> 1, h = tid & 1;     // gather assignment: 2 threads per row
    int m0 = wid * 16;                   // warp's output row slab

    // prologue: prefetch first tile's A
    issue_gather(inb, sb + SM_A0, g_tileStart[t0], g_tileCnt[t0], row, h);
    asm volatile("cp.async.commit_group;" ::: "memory");

    int curRel = -1, p = 0;
    for (int t = t0; t < t1; t++) {
        asm volatile("cp.async.wait_group 0;" ::: "memory");
        __syncthreads();

        int r = g_tileRel[t];
        if (r != curRel) {
            const char* wr = wswz + (size_t)r * 32768;
#pragma unroll
            for (int i = 0; i < 8; i++) {
                uint32_t dst = sb + SM_W + tid * 16 + i * 4096;
                asm volatile("cp.async.cg.shared.global [%0], [%1], 16;"
                             :: "r"(dst), "l"(wr + tid * 16 + i * 4096));
            }
            asm volatile("cp.async.commit_group;" ::: "memory");
            asm volatile("cp.async.wait_group 0;" ::: "memory");
            __syncthreads();
            curRel = r;
        }

        // prefetch next tile's A into the other buffer
        if (t + 1 < t1) {
            issue_gather(inb, sb + (p ? SM_A0 : SM_A1),
                         g_tileStart[t + 1], g_tileCnt[t + 1], row, h);
            asm volatile("cp.async.commit_group;" ::: "memory");
        }

        int start = g_tileStart[t], cnt = g_tileCnt[t];
        uint32_t sbA = sb + (p ? SM_A1 : SM_A0);

        // ---- 16x128x128 per warp via m16n8k16 ----
        float c[16][4];
#pragma unroll
        for (int nn = 0; nn < 16; nn++)
#pragma unroll
            for (int j = 0; j < 4; j++) c[nn][j] = 0.f;

#pragma unroll
        for (int kk = 0; kk < 8; kk++) {
            uint32_t a0, a1, a2, a3;
            uint32_t aaddr = sbA + swz(m0 + (lid & 15), kk * 32 + (lid >> 4) * 16);
            asm volatile("ldmatrix.sync.aligned.m8n8.x4.shared.b16 {%0,%1,%2,%3}, [%4];"
                         : "=r"(a0), "=r"(a1), "=r"(a2), "=r"(a3) : "r"(aaddr));
#pragma unroll
            for (int nn = 0; nn < 8; nn++) {
                uint32_t b0, b1, b2, b3;
                uint32_t baddr = sb + SM_W + swz(kk * 16 + (lid & 15), nn * 32 + (lid >> 4) * 16);
                asm volatile("ldmatrix.sync.aligned.m8n8.x4.trans.shared.b16 {%0,%1,%2,%3}, [%4];"
                             : "=r"(b0), "=r"(b1), "=r"(b2), "=r"(b3) : "r"(baddr));
                asm volatile("mma.sync.aligned.m16n8k16.row.col.f32.bf16.bf16.f32 "
                             "{%0,%1,%2,%3}, {%4,%5,%6,%7}, {%8,%9}, {%0,%1,%2,%3};"
                             : "+f"(c[2 * nn][0]), "+f"(c[2 * nn][1]),
                               "+f"(c[2 * nn][2]), "+f"(c[2 * nn][3])
                             : "r"(a0), "r"(a1), "r"(a2), "r"(a3), "r"(b0), "r"(b1));
                asm volatile("mma.sync.aligned.m16n8k16.row.col.f32.bf16.bf16.f32 "
                             "{%0,%1,%2,%3}, {%4,%5,%6,%7}, {%8,%9}, {%0,%1,%2,%3};"
                             : "+f"(c[2 * nn + 1][0]), "+f"(c[2 * nn + 1][1]),
                               "+f"(c[2 * nn + 1][2]), "+f"(c[2 * nn + 1][3])
                             : "r"(a0), "r"(a1), "r"(a2), "r"(a3), "r"(b2), "r"(b3));
            }
        }

        // ---- scatter: red.global.add directly from accumulators ----
        int r0 = m0 + (lid >> 2);
        int r1 = r0 + 8;
        int col0 = (lid & 3) * 2;
        bool act0 = r0 < cnt, act1 = r1 < cnt;
        float* p0 = act0 ? out + (size_t)g_dstS[start + r0] * HIDDEN + col0 : nullptr;
        float* p1 = act1 ? out + (size_t)g_dstS[start + r1] * HIDDEN + col0 : nullptr;
#pragma unroll
        for (int nn = 0; nn < 16; nn++) {
            if (act0)
                asm volatile("red.global.add.v2.f32 [%0], {%1,%2};"
                             :: "l"(p0 + nn * 8), "f"(c[nn][0]), "f"(c[nn][1]) : "memory");
            if (act1)
                asm volatile("red.global.add.v2.f32 [%0], {%1,%2};"
                             :: "l"(p1 + nn * 8), "f"(c[nn][2]), "f"(c[nn][3]) : "memory");
        }
        p ^= 1;
    }
}

// ---------------- launch ----------------
extern "C" void kernel_launch(void* const* d_in, const int* in_sizes, int n_in,
                              void* d_out, int out_size) {
    const int* ei = (const int*)d_in[0];     // [2, E]: row0 = dest, row1 = src
    const int* et = (const int*)d_in[1];     // [E]
    const float* emb = (const float*)d_in[2];// [N, H]
    const float* Wt = (const float*)d_in[3]; // [L, R, H, H]
    const float* Bi = (const float*)d_in[4]; // [L, R, H]
    float* out = (float*)d_out;              // [N, H]
    (void)in_sizes; (void)n_in; (void)out_size;

    void* pc; cudaGetSymbolAddress(&pc, g_cnt);
    void* prc; cudaGetSymbolAddress(&prc, g_relCount);
    void* pbuf; cudaGetSymbolAddress(&pbuf, g_buf);
    void* pwb; cudaGetSymbolAddress(&pwb, g_wbf);
    float* bufA = (float*)pbuf;
    float* bufB = bufA + (size_t)N_NODES * HIDDEN;
    const char* wb = (const char*)pwb;

    cudaMemsetAsync(pc, 0, (size_t)N_NODES * N_REL * sizeof(int));
    cudaMemsetAsync(prc, 0, N_REL * sizeof(int));

    int eb = (N_EDGES + 255) / 256;
    k_hist<<<eb, 256>>>(ei, et);
    k_tiles<<<1, 256>>>();
    k_scatter<<<eb, 256>>>(ei, et);
    k_wcvt<<<N_LAYERS * N_REL, 256>>>(Wt);

    cudaFuncSetAttribute(k_fused, cudaFuncAttributeMaxDynamicSharedMemorySize, SMEM_DYN);

    const float* lin[N_LAYERS] = {emb, bufA, bufB};
    float* lout[N_LAYERS] = {bufA, bufB, out};
    int cb = (N_NODES * HIDDEN / 8 + 255) / 256;
    for (int l = 0; l < N_LAYERS; l++) {
        k_cvt<<<cb, 256>>>(lin[l], l > 0 ? 1 : 0);
        k_bias<<<256, 256>>>(Bi + (size_t)l * N_REL * HIDDEN, lout[l]);
        k_fused<<<296, 256, SMEM_DYN>>>(wb + (size_t)l * N_REL * 32768, lout[l]);
    }
}

// round 8
// speedup vs baseline: 1.3699x; 1.0342x over previous
#include <cuda_runtime.h>
#include <cuda_bf16.h>
#include <cstdint>

#define N_NODES 50000
#define HIDDEN 128
#define N_REL 9
#define N_LAYERS 3
#define N_EDGES 600000
#define TILE_M 128
#define MAX_TILES 4800

// ---------------- device scratch (no allocations allowed) ----------------
__device__ float g_buf[2][N_NODES * HIDDEN];          // layer ping-pong fp32
__device__ __nv_bfloat16 g_inb[N_NODES * HIDDEN];     // bf16 layer input
__device__ char g_wbf[N_LAYERS * N_REL * 32768];      // pre-swizzled bf16 weights
__device__ int g_srcS[N_EDGES];
__device__ int g_dstS[N_EDGES];
__device__ int g_cnt[N_NODES * N_REL];
__device__ int g_relCount[N_REL];
__device__ int g_relCursor[N_REL];
__device__ int g_tileRel[MAX_TILES];
__device__ int g_tileStart[MAX_TILES];
__device__ int g_tileCnt[MAX_TILES];
__device__ int g_numTiles;

// ---------------- helpers ----------------
__device__ __forceinline__ uint32_t smem_u32(const void* p) {
    uint32_t a;
    asm("{ .reg .u64 t; cvta.to.shared.u64 t, %1; cvt.u32.u64 %0, t; }" : "=r"(a) : "l"(p));
    return a;
}

// 256-byte rows, XOR-swizzle 16B group index with (row & 7): conflict-free ldmatrix
__device__ __forceinline__ uint32_t swz(int row, int colByte) {
    return (uint32_t)(row * 256 + (colByte ^ ((row & 7) << 4)));
}

__device__ __forceinline__ uint4 cvt8(float4 x, float4 y, int relu) {
    if (relu) {
        x.x = fmaxf(x.x, 0.f); x.y = fmaxf(x.y, 0.f);
        x.z = fmaxf(x.z, 0.f); x.w = fmaxf(x.w, 0.f);
        y.x = fmaxf(y.x, 0.f); y.y = fmaxf(y.y, 0.f);
        y.z = fmaxf(y.z, 0.f); y.w = fmaxf(y.w, 0.f);
    }
    __nv_bfloat162 b0 = __floats2bfloat162_rn(x.x, x.y);
    __nv_bfloat162 b1 = __floats2bfloat162_rn(x.z, x.w);
    __nv_bfloat162 b2 = __floats2bfloat162_rn(y.x, y.y);
    __nv_bfloat162 b3 = __floats2bfloat162_rn(y.z, y.w);
    uint4 u;
    u.x = *(unsigned*)&b0; u.y = *(unsigned*)&b1;
    u.z = *(unsigned*)&b2; u.w = *(unsigned*)&b3;
    return u;
}

// ---------------- pre-pass kernels ----------------
__global__ void k_hist(const int* __restrict__ ei, const int* __restrict__ et) {
    __shared__ int sh[N_REL];
    int tid = threadIdx.x;
    if (tid < N_REL) sh[tid] = 0;
    __syncthreads();
    int e = blockIdx.x * blockDim.x + tid;
    if (e < N_EDGES) {
        int t = et[e];
        int d = ei[e];
        atomicAdd(&g_cnt[d * N_REL + t], 1);
        atomicAdd(&sh[t], 1);
    }
    __syncthreads();
    if (tid < N_REL && sh[tid]) atomicAdd(&g_relCount[tid], sh[tid]);
}

__global__ void k_tiles() {
    __shared__ int offs[N_REL + 1], toffs[N_REL + 1];
    if (threadIdx.x == 0) {
        int o = 0, to = 0;
        for (int r = 0; r < N_REL; r++) {
            offs[r] = o; toffs[r] = to;
            g_relCursor[r] = o;
            int c = g_relCount[r];
            o += c;
            to += (c + TILE_M - 1) / TILE_M;
        }
        offs[N_REL] = o; toffs[N_REL] = to;
        g_numTiles = to;
    }
    __syncthreads();
    for (int r = 0; r < N_REL; r++) {
        int c = g_relCount[r];
        int nt = (c + TILE_M - 1) / TILE_M;
        for (int i = threadIdx.x; i < nt; i += blockDim.x) {
            int t = toffs[r] + i;
            g_tileRel[t] = r;
            g_tileStart[t] = offs[r] + i * TILE_M;
            g_tileCnt[t] = min(TILE_M, c - i * TILE_M);
        }
    }
}

__global__ void k_scatter(const int* __restrict__ ei, const int* __restrict__ et) {
    __shared__ int sCnt[N_REL], sBase[N_REL];
    int tid = threadIdx.x;
    if (tid < N_REL) sCnt[tid] = 0;
    __syncthreads();
    int e = blockIdx.x * blockDim.x + tid;
    int t = 0, loc = 0, s = 0, d = 0;
    bool v = (e < N_EDGES);
    if (v) {
        t = et[e]; d = ei[e]; s = ei[N_EDGES + e];
        loc = atomicAdd(&sCnt[t], 1);
    }
    __syncthreads();
    if (tid < N_REL && sCnt[tid] > 0) sBase[tid] = atomicAdd(&g_relCursor[tid], sCnt[tid]);
    __syncthreads();
    if (v) {
        int pos = sBase[t] + loc;
        g_srcS[pos] = s;
        g_dstS[pos] = d;
    }
}

// pre-swizzle W[l][r] -> bf16 blocks matching smem layout (one block per (l,r))
__global__ void k_wcvt(const float* __restrict__ W) {
    int blk = blockIdx.x;                 // l*N_REL + r
    int tid = threadIdx.x;
    int row = tid >> 1, h = tid & 1;      // row = k index
    const float* src = W + ((size_t)blk * HIDDEN + row) * HIDDEN + h * 64;
    char* dst = g_wbf + (size_t)blk * 32768;
#pragma unroll
    for (int i = 0; i < 8; i++) {
        float4 x = *(const float4*)(src + i * 8);
        float4 y = *(const float4*)(src + i * 8 + 4);
        *(uint4*)(dst + swz(row, h * 128 + i * 16)) = cvt8(x, y, 0);
    }
}

// fused: fp32->bf16 convert (relu) of layer input  +  bias init of layer output
__global__ void k_prep(const float* __restrict__ in, int relu,
                       const float* __restrict__ bias, float* __restrict__ out) {
    __shared__ float sb[N_REL * HIDDEN];
    int tid = threadIdx.x, wid = tid >> 5, lid = tid & 31;
    for (int i = tid; i < N_REL * HIDDEN; i += blockDim.x) sb[i] = bias[i];
    __syncthreads();

    // part 1: convert input to bf16
    int stride = gridDim.x * blockDim.x;
    for (int i = blockIdx.x * blockDim.x + tid; i < N_NODES * HIDDEN / 8; i += stride) {
        const float4* s = (const float4*)(in + (size_t)i * 8);
        float4 x = s[0], y = s[1];
        *(uint4*)(g_inb + (size_t)i * 8) = cvt8(x, y, relu);
    }

    // part 2: out[d] = sum_r cnt[d][r] * bias[r]
    int warps = gridDim.x * (blockDim.x >> 5);
    for (int node = blockIdx.x * (blockDim.x >> 5) + wid; node < N_NODES; node += warps) {
        const int* c = &g_cnt[node * N_REL];
        float4 acc = make_float4(0.f, 0.f, 0.f, 0.f);
#pragma unroll
        for (int r = 0; r < N_REL; r++) {
            float cf = (float)__ldg(&c[r]);
            float4 b = *(const float4*)&sb[r * HIDDEN + lid * 4];
            acc.x += cf * b.x; acc.y += cf * b.y;
            acc.z += cf * b.z; acc.w += cf * b.w;
        }
        *(float4*)&out[(size_t)node * HIDDEN + lid * 4] = acc;
    }
}

// ---------------- fused gather + mma.sync + scatter (cp.async pipelined) -------
static constexpr int SM_W = 0;       // 32 KB: W_r bf16 swizzled
static constexpr int SM_A0 = 32768;  // 32 KB: A tile buf 0
static constexpr int SM_A1 = 65536;  // 32 KB: A tile buf 1
static constexpr int SMEM_DYN = 98304 + 512;

__device__ __forceinline__ void issue_gather(const char* inb, uint32_t sbA,
                                             int start, int cnt, int row, int h) {
    int sz = (row < cnt) ? 16 : 0;
    int node = (row < cnt) ? g_srcS[start + row] : 0;
    const char* src = inb + (size_t)node * 256 + h * 128;
#pragma unroll
    for (int i = 0; i < 8; i++) {
        uint32_t dst = sbA + swz(row, h * 128 + i * 16);
        asm volatile("cp.async.cg.shared.global [%0], [%1], 16, %2;"
                     :: "r"(dst), "l"(src + i * 16), "r"(sz));
    }
}

__global__ void __launch_bounds__(256, 2)
k_fused(const char* __restrict__ wswz, float* __restrict__ out) {
    extern __shared__ char smraw[];
    uint32_t sbRaw = smem_u32(smraw);
    uint32_t sb = (sbRaw + 255) & ~255u;
    int tid = threadIdx.x, wid = tid >> 5, lid = tid & 31;

    const char* inb = (const char*)g_inb;

    int T = g_numTiles;
    int per = (T + gridDim.x - 1) / gridDim.x;
    int t0 = blockIdx.x * per;
    int t1 = min(T, t0 + per);
    if (t0 >= t1) return;

    int row = tid >> 1, h = tid & 1;   // gather assignment: 2 threads per row
    // warp tiling: 32 rows x 64 cols
    int m0 = (wid & 3) * 32;           // warp's row slab
    int n0 = (wid >> 2) * 64;          // warp's col slab
    int q = lid & 3;

    // prologue: prefetch first tile's A
    issue_gather(inb, sb + SM_A0, g_tileStart[t0], g_tileCnt[t0], row, h);
    asm volatile("cp.async.commit_group;" ::: "memory");

    int curRel = -1, p = 0;
    for (int t = t0; t < t1; t++) {
        asm volatile("cp.async.wait_group 0;" ::: "memory");
        __syncthreads();

        int r = g_tileRel[t];
        if (r != curRel) {
            const char* wr = wswz + (size_t)r * 32768;
#pragma unroll
            for (int i = 0; i < 8; i++) {
                uint32_t dst = sb + SM_W + tid * 16 + i * 4096;
                asm volatile("cp.async.cg.shared.global [%0], [%1], 16;"
                             :: "r"(dst), "l"(wr + tid * 16 + i * 4096));
            }
            asm volatile("cp.async.commit_group;" ::: "memory");
            asm volatile("cp.async.wait_group 0;" ::: "memory");
            __syncthreads();
            curRel = r;
        }

        // prefetch next tile's A into the other buffer
        if (t + 1 < t1) {
            issue_gather(inb, sb + (p ? SM_A0 : SM_A1),
                         g_tileStart[t + 1], g_tileCnt[t + 1], row, h);
            asm volatile("cp.async.commit_group;" ::: "memory");
        }

        int start = g_tileStart[t], cnt = g_tileCnt[t];
        uint32_t sbA = sb + (p ? SM_A1 : SM_A0);

        // ---- 32x64x128 per warp via m16n8k16: c[mh][nn] = rows m0+mh*16, cols n0+nn*8
        float c[2][8][4];
#pragma unroll
        for (int mh = 0; mh < 2; mh++)
#pragma unroll
            for (int nn = 0; nn < 8; nn++)
#pragma unroll
                for (int j = 0; j < 4; j++) c[mh][nn][j] = 0.f;

#pragma unroll
        for (int kk = 0; kk < 8; kk++) {
            uint32_t a[2][4];
#pragma unroll
            for (int mh = 0; mh < 2; mh++) {
                uint32_t aaddr = sbA + swz(m0 + mh * 16 + (lid & 15), kk * 32 + (lid >> 4) * 16);
                asm volatile("ldmatrix.sync.aligned.m8n8.x4.shared.b16 {%0,%1,%2,%3}, [%4];"
                             : "=r"(a[mh][0]), "=r"(a[mh][1]), "=r"(a[mh][2]), "=r"(a[mh][3])
                             : "r"(aaddr));
            }
#pragma unroll
            for (int nn2 = 0; nn2 < 4; nn2++) {
                uint32_t b0, b1, b2, b3;
                uint32_t baddr = sb + SM_W +
                    swz(kk * 16 + (lid & 15), n0 * 2 + nn2 * 32 + (lid >> 4) * 16);
                asm volatile("ldmatrix.sync.aligned.m8n8.x4.trans.shared.b16 {%0,%1,%2,%3}, [%4];"
                             : "=r"(b0), "=r"(b1), "=r"(b2), "=r"(b3) : "r"(baddr));
#pragma unroll
                for (int mh = 0; mh < 2; mh++) {
                    asm volatile("mma.sync.aligned.m16n8k16.row.col.f32.bf16.bf16.f32 "
                                 "{%0,%1,%2,%3}, {%4,%5,%6,%7}, {%8,%9}, {%0,%1,%2,%3};"
                                 : "+f"(c[mh][2 * nn2][0]), "+f"(c[mh][2 * nn2][1]),
                                   "+f"(c[mh][2 * nn2][2]), "+f"(c[mh][2 * nn2][3])
                                 : "r"(a[mh][0]), "r"(a[mh][1]), "r"(a[mh][2]), "r"(a[mh][3]),
                                   "r"(b0), "r"(b1));
                    asm volatile("mma.sync.aligned.m16n8k16.row.col.f32.bf16.bf16.f32 "
                                 "{%0,%1,%2,%3}, {%4,%5,%6,%7}, {%8,%9}, {%0,%1,%2,%3};"
                                 : "+f"(c[mh][2 * nn2 + 1][0]), "+f"(c[mh][2 * nn2 + 1][1]),
                                   "+f"(c[mh][2 * nn2 + 1][2]), "+f"(c[mh][2 * nn2 + 1][3])
                                 : "r"(a[mh][0]), "r"(a[mh][1]), "r"(a[mh][2]), "r"(a[mh][3]),
                                   "r"(b2), "r"(b3));
                }
            }
        }

        // ---- scatter: shuffle-pack quads into red.global.add.v4 ----
        // within a quad all 4 threads share rows (r0, r1); thread q holds cols 2q,2q+1.
        // exchange across lid^1: even lane assembles 4 cols of r0, odd lane 4 cols of r1.
        bool even = (q & 1) == 0;
#pragma unroll
        for (int mh = 0; mh < 2; mh++) {
            int r0 = m0 + mh * 16 + (lid >> 2);
            int r1 = r0 + 8;
            int myrow = even ? r0 : r1;
            bool act = myrow < cnt;
            float* pbase = act
                ? out + (size_t)g_dstS[start + myrow] * HIDDEN + n0 + (q >> 1) * 4
                : nullptr;
#pragma unroll
            for (int nn = 0; nn < 8; nn++) {
                float s0 = even ? c[mh][nn][2] : c[mh][nn][0];
                float s1 = even ? c[mh][nn][3] : c[mh][nn][1];
                float p0 = __shfl_xor_sync(0xffffffffu, s0, 1);
                float p1 = __shfl_xor_sync(0xffffffffu, s1, 1);
                float v0, v1, v2, v3;
                if (even) { v0 = c[mh][nn][0]; v1 = c[mh][nn][1]; v2 = p0; v3 = p1; }
                else      { v0 = p0; v1 = p1; v2 = c[mh][nn][2]; v3 = c[mh][nn][3]; }
                if (act)
                    asm volatile("red.global.add.v4.f32 [%0], {%1,%2,%3,%4};"
                                 :: "l"(pbase + nn * 8),
                                    "f"(v0), "f"(v1), "f"(v2), "f"(v3) : "memory");
            }
        }
        p ^= 1;
    }
}

// ---------------- launch ----------------
extern "C" void kernel_launch(void* const* d_in, const int* in_sizes, int n_in,
                              void* d_out, int out_size) {
    const int* ei = (const int*)d_in[0];     // [2, E]: row0 = dest, row1 = src
    const int* et = (const int*)d_in[1];     // [E]
    const float* emb = (const float*)d_in[2];// [N, H]
    const float* Wt = (const float*)d_in[3]; // [L, R, H, H]
    const float* Bi = (const float*)d_in[4]; // [L, R, H]
    float* out = (float*)d_out;              // [N, H]
    (void)in_sizes; (void)n_in; (void)out_size;

    void* pc; cudaGetSymbolAddress(&pc, g_cnt);
    void* prc; cudaGetSymbolAddress(&prc, g_relCount);
    void* pbuf; cudaGetSymbolAddress(&pbuf, g_buf);
    void* pwb; cudaGetSymbolAddress(&pwb, g_wbf);
    float* bufA = (float*)pbuf;
    float* bufB = bufA + (size_t)N_NODES * HIDDEN;
    const char* wb = (const char*)pwb;

    cudaMemsetAsync(pc, 0, (size_t)N_NODES * N_REL * sizeof(int));
    cudaMemsetAsync(prc, 0, N_REL * sizeof(int));

    int eb = (N_EDGES + 255) / 256;
    k_hist<<<eb, 256>>>(ei, et);
    k_tiles<<<1, 256>>>();
    k_scatter<<<eb, 256>>>(ei, et);
    k_wcvt<<<N_LAYERS * N_REL, 256>>>(Wt);

    cudaFuncSetAttribute(k_fused, cudaFuncAttributeMaxDynamicSharedMemorySize, SMEM_DYN);

    const float* lin[N_LAYERS] = {emb, bufA, bufB};
    float* lout[N_LAYERS] = {bufA, bufB, out};
    for (int l = 0; l < N_LAYERS; l++) {
        k_prep<<<256, 256>>>(lin[l], l > 0 ? 1 : 0,
                             Bi + (size_t)l * N_REL * HIDDEN, lout[l]);
        k_fused<<<296, 256, SMEM_DYN>>>(wb + (size_t)l * N_REL * 32768, lout[l]);
    }
}